// round 10
// baseline (speedup 1.0000x reference)
#include <cuda_runtime.h>

// FeatNeighbourCorr R7: R5 2-stage cp.async pipeline, KC=8 (16 iterations).
// out[b,k,h,w] = <n_p, n_q>, n = f/||f||_C, q = reflect(p - d_k).
// Tile 16(h) x 32(w), 128 threads, 8-channel chunks.

#define HH 256
#define WW 256
#define CC 128
#define HW (HH * WW)
#define TH 16
#define TW 32
#define KC 8
#define NCH (CC / KC)        // 16 chunk iterations
#define SR 18                // staged rows  (h0-1 .. h0+16)
#define SPC 18               // staged float2 per row (cols w0-2 .. w0+33)
#define SSTR2 19             // padded float2 stride
#define PLANE2 (SR * SSTR2)  // 342 float2 per channel plane
#define BUF2 (KC * PLANE2)   // 2736 float2 per buffer
#define NSLOTP (SR * SPC)    // 324 pixel-pair slots
#define NT 128
#define RNSTR 35

typedef unsigned long long u64;

__device__ __forceinline__ u64 pack2(float lo, float hi) {
    u64 r; asm("mov.b64 %0, {%1,%2};" : "=l"(r) : "f"(lo), "f"(hi)); return r;
}
__device__ __forceinline__ float lo2(u64 a) { return __uint_as_float((unsigned)a); }
__device__ __forceinline__ float hi2(u64 a) { return __uint_as_float((unsigned)(a >> 32)); }
__device__ __forceinline__ void fma2(u64& d, u64 a, u64 b) {
    asm("fma.rn.f32x2 %0, %1, %2, %0;" : "+l"(d) : "l"(a), "l"(b));
}
__device__ __forceinline__ u64 mul2(u64 a, u64 b) {
    u64 r; asm("mul.rn.f32x2 %0, %1, %2;" : "=l"(r) : "l"(a), "l"(b)); return r;
}
__device__ __forceinline__ int refl(int x) {
    return x < 0 ? -x : (x > HH - 1 ? 2 * (HH - 1) - x : x);
}

__global__ __launch_bounds__(NT, 5)
void featcorr_r7(const float* __restrict__ feats, float* __restrict__ out) {
    __shared__ u64 pool[2 * BUF2];   // 43776 B
    const int t  = threadIdx.x;
    const int b  = blockIdx.z;
    const int h0 = blockIdx.y * TH;
    const int w0 = blockIdx.x * TW;
    const unsigned sbase = (unsigned)__cvta_generic_to_shared(pool);

    // ---- pixel-pair slots (row, pc); channel handled by inner loop ----
    int src[3]; unsigned dst[3]; bool valp[3];
#pragma unroll
    for (int u = 0; u < 3; ++u) {
        int s = t + NT * u;
        bool in = s < NSLOTP;
        int ss = in ? s : 0;
        int row = ss / SPC, pc = ss - row * SPC;
        int gh = refl(h0 - 1 + row);
        int gc = w0 - 2 + 2 * pc;
        bool edge = (gc < 0) || (gc >= WW - 1);
        valp[u] = in && !edge;
        src[u] = gh * WW + gc;
        dst[u] = sbase + (unsigned)((row * SSTR2 + pc) * 8);
    }

    // ---- scalar slots for reflected w-edge pairs: KC*SR = 144 slots ----
    const bool etile = (w0 == 0 || w0 == WW - TW);
    const bool eactA = etile;              // slot t      (t < 128 < 144)
    const bool eactB = etile && (t < 16);  // slot 128+t
    int esA = 0, eiA = 0, esB = 0, eiB = 0;
    {
        int sA = t, sB = 128 + t;
        int chA = sA / SR, rowA = sA - chA * SR;
        int chB = sB / SR, rowB = sB - chB * SR;
        int ghA = refl(h0 - 1 + rowA);
        int ghB = refl(h0 - 1 + rowB);
        if (w0 == 0) {
            esA = chA * HW + ghA * WW + 2;
            esB = chB * HW + ghB * WW + 2;
            eiA = chA * PLANE2 + rowA * SSTR2 + 0;
            eiB = chB * PLANE2 + rowB * SSTR2 + 0;
        } else {
            esA = chA * HW + ghA * WW + 254;
            esB = chB * HW + ghB * WW + 254;
            eiA = chA * PLANE2 + rowA * SSTR2 + 17;
            eiB = chB * PLANE2 + rowB * SSTR2 + 17;
        }
    }

    // ---- halo-ring ssq slot (100 ring pixels) ----
    const bool ract = t < 100;
    int roff = 0, rnoff = 0;
    if (ract) {
        int rrow, rcol;
        if (t < 34)       { rrow = 0;       rcol = 1 + t; }
        else if (t < 68)  { rrow = SR - 1;  rcol = 1 + t - 34; }
        else if (t < 84)  { rrow = t - 67;  rcol = 1; }
        else              { rrow = t - 83;  rcol = 34; }
        roff  = rrow * (SSTR2 * 2) + rcol;
        rnoff = rrow * RNSTR + rcol;
    }

    const int py = t >> 3, pxg = t & 7;
    const int sc0 = 2 * pxg;

    u64 acc0[8], acc1[8];
#pragma unroll
    for (int k = 0; k < 8; ++k) { acc0[k] = 0ull; acc1[k] = 0ull; }
    u64 ssq01 = 0ull, ssq23 = 0ull;
    float rss = 0.f;
    float exA = 0.f, eyA = 0.f, exB = 0.f, eyB = 0.f;

    const float* bp = feats + (size_t)b * CC * HW;

    // ---- prologue: chunk 0 into buffer 0 ----
    {
#pragma unroll
        for (int u = 0; u < 3; ++u) {
            if (valp[u]) {
#pragma unroll
                for (int ch = 0; ch < KC; ++ch)
                    asm volatile("cp.async.ca.shared.global [%0], [%1], 8;"
                                 :: "r"(dst[u] + (unsigned)(ch * PLANE2 * 8)),
                                    "l"(bp + src[u] + ch * HW) : "memory");
            }
        }
        asm volatile("cp.async.commit_group;" ::: "memory");
        if (eactA) { exA = __ldg(bp + esA); eyA = __ldg(bp + esA - 1); }
        if (eactB) { exB = __ldg(bp + esB); eyB = __ldg(bp + esB - 1); }
    }

    for (int it = 0; it < NCH; ++it) {
        asm volatile("cp.async.wait_group 0;" ::: "memory");
        const unsigned cb = (unsigned)(it & 1) * BUF2;
        if (eactA)
            reinterpret_cast<float2*>(pool)[cb + eiA] = make_float2(exA, eyA);
        if (eactB)
            reinterpret_cast<float2*>(pool)[cb + eiB] = make_float2(exB, eyB);
        __syncthreads();

        if (it + 1 < NCH) {
            const float* bn = bp + KC * HW;
            const unsigned bo = (unsigned)(((it + 1) & 1) * BUF2 * 8);
#pragma unroll
            for (int u = 0; u < 3; ++u) {
                if (valp[u]) {
#pragma unroll
                    for (int ch = 0; ch < KC; ++ch)
                        asm volatile("cp.async.ca.shared.global [%0], [%1], 8;"
                                     :: "r"(dst[u] + bo + (unsigned)(ch * PLANE2 * 8)),
                                        "l"(bn + src[u] + ch * HW) : "memory");
                }
            }
            asm volatile("cp.async.commit_group;" ::: "memory");
            if (eactA) { exA = __ldg(bn + esA); eyA = __ldg(bn + esA - 1); }
            if (eactB) { exB = __ldg(bn + esB); eyB = __ldg(bn + esB - 1); }
        }

        const u64* B = pool + cb;
#pragma unroll
        for (int ch = 0; ch < KC; ++ch) {
            const u64* tp = B + ch * PLANE2 + py * SSTR2 + sc0;
            u64 t0 = tp[0], t1 = tp[1], t2 = tp[2], t3 = tp[3];
            const u64* mp = tp + SSTR2;
            u64 m0 = mp[0], m1 = mp[1], m2 = mp[2], m3 = mp[3];
            const u64* bq = mp + SSTR2;
            u64 b0 = bq[0], b1 = bq[1], b2 = bq[2], b3 = bq[3];

            u64 tL = pack2(hi2(t0), lo2(t1)), tM = pack2(hi2(t1), lo2(t2)), tR = pack2(hi2(t2), lo2(t3));
            u64 mL = pack2(hi2(m0), lo2(m1)), mM = pack2(hi2(m1), lo2(m2)), mR = pack2(hi2(m2), lo2(m3));
            u64 bL = pack2(hi2(b0), lo2(b1)), bM = pack2(hi2(b1), lo2(b2)), bR = pack2(hi2(b2), lo2(b3));

            fma2(acc0[0], m1, t1); fma2(acc0[1], m1, tL);
            fma2(acc0[2], m1, mL); fma2(acc0[3], m1, bL);
            fma2(acc0[4], m1, b1); fma2(acc0[5], m1, bM);
            fma2(acc0[6], m1, mM); fma2(acc0[7], m1, tM);

            fma2(acc1[0], m2, t2); fma2(acc1[1], m2, tM);
            fma2(acc1[2], m2, mM); fma2(acc1[3], m2, bM);
            fma2(acc1[4], m2, b2); fma2(acc1[5], m2, bR);
            fma2(acc1[6], m2, mR); fma2(acc1[7], m2, tR);

            fma2(ssq01, m1, m1);   fma2(ssq23, m2, m2);

            if (ract) {
                float rv = reinterpret_cast<const float*>(B)[ch * (PLANE2 * 2) + roff];
                rss += rv * rv;
            }
        }
        bp += KC * HW;
    }

    // ---- norms: centers in regs, ring via smem map (aliased over buffer 0) ----
    float rp0 = rsqrtf(lo2(ssq01)), rp1 = rsqrtf(hi2(ssq01));
    float rp2 = rsqrtf(lo2(ssq23)), rp3 = rsqrtf(hi2(ssq23));
    float* RN = reinterpret_cast<float*>(pool);   // 18 x 35 floats
    {
        int cbx = (py + 1) * RNSTR + sc0 * 2 + 2;
        RN[cbx] = rp0; RN[cbx + 1] = rp1; RN[cbx + 2] = rp2; RN[cbx + 3] = rp3;
    }
    if (ract) RN[rnoff] = rsqrtf(rss);
    __syncthreads();

    // ---- gather neighbor norms, scale, store float4 per offset ----
    const int DXa[8] = {1, 1, 0, -1, -1, -1, 0, 1};
    const int DYa[8] = {0, 1, 1, 1, 0, -1, -1, -1};
    const int h = h0 + py;
    const int wb = w0 + 4 * pxg;
    const u64 rp01 = pack2(rp0, rp1), rp23 = pack2(rp2, rp3);
    float* ob = out + ((size_t)b * 8) * HW + (size_t)h * WW + wb;
#pragma unroll
    for (int k = 0; k < 8; ++k) {
        int qsr = refl(h - DXa[k]) - (h0 - 1);
        float rq[4];
#pragma unroll
        for (int i = 0; i < 4; ++i) {
            int qw = refl(wb + i - DYa[k]);
            rq[i] = RN[qsr * RNSTR + (qw - w0 + 2)];
        }
        u64 o01 = mul2(mul2(acc0[k], rp01), pack2(rq[0], rq[1]));
        u64 o23 = mul2(mul2(acc1[k], rp23), pack2(rq[2], rq[3]));
        float4 v = make_float4(lo2(o01), hi2(o01), lo2(o23), hi2(o23));
        *reinterpret_cast<float4*>(ob + (size_t)k * HW) = v;
    }
}

extern "C" void kernel_launch(void* const* d_in, const int* in_sizes, int n_in,
                              void* d_out, int out_size) {
    const float* feats = (const float*)d_in[0];
    float* out = (float*)d_out;
    dim3 grid(WW / TW, HH / TH, 8);
    featcorr_r7<<<grid, NT>>>(feats, out);
}

// round 11
// speedup vs baseline: 1.3715x; 1.3715x over previous
#include <cuda_runtime.h>

// FeatNeighbourCorr R8: R5 pipeline + LDS.128 compute loads (stride-20 layout).
// out[b,k,h,w] = <n_p, n_q>, n = f/||f||_C, q = reflect(p - d_k).
// Tile 16(h) x 32(w), 128 threads, 4-channel chunks, 32 pipelined iterations.

#define HH 256
#define WW 256
#define CC 128
#define HW (HH * WW)
#define TH 16
#define TW 32
#define KC 4
#define NCH (CC / KC)        // 32 chunk iterations
#define SR 18                // staged rows  (h0-1 .. h0+16)
#define SPC 18               // staged float2 per row (cols w0-2 .. w0+33)
#define SSTR2 20             // padded float2 stride (16B-aligned rows)
#define PLANE2 (SR * SSTR2)  // 360 float2 per channel plane
#define BUF2 (KC * PLANE2)   // 1440 float2 per buffer
#define NSLOT (KC * SR * SPC) // 1296 cp slots
#define NT 128
#define RNSTR 35

typedef unsigned long long u64;

__device__ __forceinline__ u64 pack2(float lo, float hi) {
    u64 r; asm("mov.b64 %0, {%1,%2};" : "=l"(r) : "f"(lo), "f"(hi)); return r;
}
__device__ __forceinline__ float lo2(u64 a) { return __uint_as_float((unsigned)a); }
__device__ __forceinline__ float hi2(u64 a) { return __uint_as_float((unsigned)(a >> 32)); }
__device__ __forceinline__ void fma2(u64& d, u64 a, u64 b) {
    asm("fma.rn.f32x2 %0, %1, %2, %0;" : "+l"(d) : "l"(a), "l"(b));
}
__device__ __forceinline__ u64 mul2(u64 a, u64 b) {
    u64 r; asm("mul.rn.f32x2 %0, %1, %2;" : "=l"(r) : "l"(a), "l"(b)); return r;
}
__device__ __forceinline__ int refl(int x) {
    return x < 0 ? -x : (x > HH - 1 ? 2 * (HH - 1) - x : x);
}

__global__ __launch_bounds__(NT, 5)
void featcorr_r8(const float* __restrict__ feats, float* __restrict__ out) {
    __shared__ u64 pool[2 * BUF2];   // 23040 B
    const int t  = threadIdx.x;
    const int b  = blockIdx.z;
    const int h0 = blockIdx.y * TH;
    const int w0 = blockIdx.x * TW;
    const unsigned sbase = (unsigned)__cvta_generic_to_shared(pool);

    // ---- cp.async slots over (ch, row, pc), chunk-invariant ----
    int src[11]; unsigned dst[11]; bool val[11];
#pragma unroll
    for (int u = 0; u < 11; ++u) {
        int s = t + NT * u;
        bool in = s < NSLOT;
        int ss = in ? s : 0;
        int ch = ss / (SR * SPC);
        int r  = ss - ch * (SR * SPC);
        int row = r / SPC, pc = r - row * SPC;
        int gh = refl(h0 - 1 + row);
        int gc = w0 - 2 + 2 * pc;
        bool edge = (gc < 0) || (gc >= WW - 1);   // pair straddles image border
        val[u] = in && !edge;
        src[u] = ch * HW + gh * WW + gc;
        dst[u] = sbase + (unsigned)((ch * PLANE2 + row * SSTR2 + pc) * 8);
    }

    // ---- scalar slots for reflected w-edge pairs (edge tiles only) ----
    const bool eact = (w0 == 0 || w0 == WW - TW) && (t < KC * SR);  // 72 threads
    int es0 = 0, es1 = 0, eidx = 0;
    if (eact) {
        int ch = t / SR, row = t - ch * SR;
        int gh = refl(h0 - 1 + row);
        if (w0 == 0) {  // pair (-2,-1) -> (f[2], f[1])
            es0 = ch * HW + gh * WW + 2;  es1 = es0 - 1;
            eidx = ch * PLANE2 + row * SSTR2 + 0;
        } else {        // pair (256,257) -> (f[254], f[253])
            es0 = ch * HW + gh * WW + 254; es1 = es0 - 1;
            eidx = ch * PLANE2 + row * SSTR2 + 17;
        }
    }

    // ---- halo-ring ssq slot (100 ring pixels) ----
    const bool ract = t < 100;
    int roff = 0, rnoff = 0;
    if (ract) {
        int rrow, rcol;
        if (t < 34)       { rrow = 0;       rcol = 1 + t; }
        else if (t < 68)  { rrow = SR - 1;  rcol = 1 + t - 34; }
        else if (t < 84)  { rrow = t - 67;  rcol = 1; }
        else              { rrow = t - 83;  rcol = 34; }
        roff  = rrow * (SSTR2 * 2) + rcol;   // float index within ch plane
        rnoff = rrow * RNSTR + rcol;
    }

    const int py = t >> 3, pxg = t & 7;
    const int sc0 = 2 * pxg;

    u64 acc0[8], acc1[8];
#pragma unroll
    for (int k = 0; k < 8; ++k) { acc0[k] = 0ull; acc1[k] = 0ull; }
    u64 ssq01 = 0ull, ssq23 = 0ull;
    float rss = 0.f;
    float ex = 0.f, ey = 0.f;

    const float* bp = feats + (size_t)b * CC * HW;

    // prologue: chunk 0
    {
#pragma unroll
        for (int u = 0; u < 11; ++u)
            if (val[u])
                asm volatile("cp.async.ca.shared.global [%0], [%1], 8;"
                             :: "r"(dst[u]), "l"(bp + src[u]) : "memory");
        asm volatile("cp.async.commit_group;" ::: "memory");
        if (eact) { ex = __ldg(bp + es0); ey = __ldg(bp + es1); }
    }

    for (int it = 0; it < NCH; ++it) {
        asm volatile("cp.async.wait_group 0;" ::: "memory");
        if (eact)
            reinterpret_cast<float2*>(pool)[(it & 1) * BUF2 + eidx] = make_float2(ex, ey);
        __syncthreads();

        if (it + 1 < NCH) {
            const float* bn = bp + KC * HW;
            unsigned bo = (unsigned)(((it + 1) & 1) * BUF2 * 8);
#pragma unroll
            for (int u = 0; u < 11; ++u)
                if (val[u])
                    asm volatile("cp.async.ca.shared.global [%0], [%1], 8;"
                                 :: "r"(dst[u] + bo), "l"(bn + src[u]) : "memory");
            asm volatile("cp.async.commit_group;" ::: "memory");
            if (eact) { ex = __ldg(bn + es0); ey = __ldg(bn + es1); }
        }

        const u64* B = pool + (it & 1) * BUF2;
#pragma unroll
        for (int ch = 0; ch < KC; ++ch) {
            // 16B-aligned 3x8-float window: 6 x LDS.128
            const float4* W = reinterpret_cast<const float4*>(
                B + ch * PLANE2 + py * SSTR2 + sc0);
            float4 Ta = W[0], Tb = W[1];
            const float4* Wm = reinterpret_cast<const float4*>(
                B + ch * PLANE2 + (py + 1) * SSTR2 + sc0);
            float4 Ma = Wm[0], Mb = Wm[1];
            const float4* Wb = reinterpret_cast<const float4*>(
                B + ch * PLANE2 + (py + 2) * SSTR2 + sc0);
            float4 Ba = Wb[0], Bb = Wb[1];

            u64 t1 = pack2(Ta.z, Ta.w), t2 = pack2(Tb.x, Tb.y);
            u64 m1 = pack2(Ma.z, Ma.w), m2 = pack2(Mb.x, Mb.y);
            u64 b1 = pack2(Ba.z, Ba.w), b2 = pack2(Bb.x, Bb.y);

            u64 tL = pack2(Ta.y, Ta.z), tM = pack2(Ta.w, Tb.x), tR = pack2(Tb.y, Tb.z);
            u64 mL = pack2(Ma.y, Ma.z), mM = pack2(Ma.w, Mb.x), mR = pack2(Mb.y, Mb.z);
            u64 bL = pack2(Ba.y, Ba.z), bM = pack2(Ba.w, Bb.x), bR = pack2(Bb.y, Bb.z);

            fma2(acc0[0], m1, t1); fma2(acc0[1], m1, tL);
            fma2(acc0[2], m1, mL); fma2(acc0[3], m1, bL);
            fma2(acc0[4], m1, b1); fma2(acc0[5], m1, bM);
            fma2(acc0[6], m1, mM); fma2(acc0[7], m1, tM);

            fma2(acc1[0], m2, t2); fma2(acc1[1], m2, tM);
            fma2(acc1[2], m2, mM); fma2(acc1[3], m2, bM);
            fma2(acc1[4], m2, b2); fma2(acc1[5], m2, bR);
            fma2(acc1[6], m2, mR); fma2(acc1[7], m2, tR);

            fma2(ssq01, m1, m1);   fma2(ssq23, m2, m2);

            if (ract) {
                float rv = reinterpret_cast<const float*>(B)[ch * (PLANE2 * 2) + roff];
                rss += rv * rv;
            }
        }
        bp += KC * HW;
    }

    // ---- norms: centers in regs, ring via smem map (aliased over buffer 0) ----
    float rp0 = rsqrtf(lo2(ssq01)), rp1 = rsqrtf(hi2(ssq01));
    float rp2 = rsqrtf(lo2(ssq23)), rp3 = rsqrtf(hi2(ssq23));
    float* RN = reinterpret_cast<float*>(pool);   // 18 x 35 floats, fits in buf0
    {
        int cb = (py + 1) * RNSTR + sc0 * 2 + 2;
        RN[cb] = rp0; RN[cb + 1] = rp1; RN[cb + 2] = rp2; RN[cb + 3] = rp3;
    }
    if (ract) RN[rnoff] = rsqrtf(rss);
    __syncthreads();

    // ---- gather neighbor norms, scale, store float4 per offset ----
    const int DXa[8] = {1, 1, 0, -1, -1, -1, 0, 1};
    const int DYa[8] = {0, 1, 1, 1, 0, -1, -1, -1};
    const int h = h0 + py;
    const int wb = w0 + 4 * pxg;
    const u64 rp01 = pack2(rp0, rp1), rp23 = pack2(rp2, rp3);
    float* ob = out + ((size_t)b * 8) * HW + (size_t)h * WW + wb;
#pragma unroll
    for (int k = 0; k < 8; ++k) {
        int qsr = refl(h - DXa[k]) - (h0 - 1);
        float rq[4];
#pragma unroll
        for (int i = 0; i < 4; ++i) {
            int qw = refl(wb + i - DYa[k]);
            rq[i] = RN[qsr * RNSTR + (qw - w0 + 2)];
        }
        u64 o01 = mul2(mul2(acc0[k], rp01), pack2(rq[0], rq[1]));
        u64 o23 = mul2(mul2(acc1[k], rp23), pack2(rq[2], rq[3]));
        float4 v = make_float4(lo2(o01), hi2(o01), lo2(o23), hi2(o23));
        *reinterpret_cast<float4*>(ob + (size_t)k * HW) = v;
    }
}

extern "C" void kernel_launch(void* const* d_in, const int* in_sizes, int n_in,
                              void* d_out, int out_size) {
    const float* feats = (const float*)d_in[0];
    float* out = (float*)d_out;
    dim3 grid(WW / TW, HH / TH, 8);
    featcorr_r8<<<grid, NT>>>(feats, out);
}